// round 17
// baseline (speedup 1.0000x reference)
#include <cuda_runtime.h>
#include <cstddef>

// ---------------------------------------------------------------------------
// Problem constants
// ---------------------------------------------------------------------------
constexpr int B_  = 2;
constexpr int C_  = 64;
constexpr int C4_ = 256;
constexpr int H_  = 64;
constexpr int W_  = 96;
constexpr int HW_ = H_ * W_;
constexpr int NSB = 2 * B_;   // side * batch slots

typedef unsigned long long ull;

// Scratch (device globals: no allocations allowed).
__device__ float g_t1[(size_t)NSB * C4_ * HW_];
__device__ float g_t2[(size_t)NSB * C4_ * HW_];
__device__ float g_Q4[(size_t)B_ * C_ * HW_];        // quad-interleaved Q
__device__ float g_K4[(size_t)B_ * C_ * HW_];        // quad-interleaved K
__device__ float g_X4[(size_t)2 * B_ * C_ * HW_];    // quad-interleaved xL,xR

// ---------------------------------------------------------------------------
// f32x2 helpers (sm_100+ packed fp32 — exact, two independent IEEE FMAs)
// ---------------------------------------------------------------------------
__device__ __forceinline__ ull pk2(float a, float b) {
    ull r;
    asm("mov.b64 %0, {%1, %2};" : "=l"(r)
        : "r"(__float_as_uint(a)), "r"(__float_as_uint(b)));
    return r;
}
__device__ __forceinline__ void fma2(ull& d, ull a, ull b) {
    asm("fma.rn.f32x2 %0, %1, %2, %0;" : "+l"(d) : "l"(a), "l"(b));
}
__device__ __forceinline__ void unpk2(ull v, float& lo, float& hi) {
    unsigned l, h;
    asm("mov.b64 {%0, %1}, %2;" : "=r"(l), "=r"(h) : "l"(v));
    lo = __uint_as_float(l); hi = __uint_as_float(h);
}

// ---------------------------------------------------------------------------
// Repack xL/xR into quad-interleaved layout [side][b][quad=ch/4][h][w][4].
// ---------------------------------------------------------------------------
__global__ __launch_bounds__(256)
void repack_kernel(const float* __restrict__ xL, const float* __restrict__ xR,
                   float* __restrict__ X4)
{
    const int idx = blockIdx.x * 256 + threadIdx.x;   // 2*B*16*HW items
    if (idx >= 2 * B_ * 16 * HW_) return;
    const int pix = idx % HW_;
    const int q   = (idx / HW_) % 16;
    const int b   = (idx / (16 * HW_)) % B_;
    const int s   = idx / (B_ * 16 * HW_);
    const float* src = (s ? xR : xL) + (size_t)(b * C_ + q * 4) * HW_ + pix;
    float4 v;
    v.x = src[0];
    v.y = src[HW_];
    v.z = src[2 * HW_];
    v.w = src[3 * HW_];
    ((float4*)X4)[idx] = v;
}

// ---------------------------------------------------------------------------
// Grouped 3x3 conv (R15 measured-best — FROZEN). OC-split, 32 oc/block,
// register-prefetch pipeline, BN-on-load for MODE1 (boundary-correct).
// ---------------------------------------------------------------------------
constexpr int TH   = 8;
constexpr int TW   = 32;
constexpr int ICB  = 8;
constexpr int INROW   = TW + 2;   // 34 valid cols
constexpr int INPITCH = 36;

constexpr int IN_ELEMS  = ICB * 10 * INROW;        // 2720
constexpr int CONV_W2   = 32 * 72;                 // 2304 ull
constexpr int CONV_IN   = ICB * 10 * INPITCH;      // 2880 floats
constexpr int CONV_SMEM = CONV_W2 * 8 + CONV_IN * 4 + 2 * 64 * 4;

template <int MODE>
__global__ __launch_bounds__(256, 3)
void conv3x3_kernel(const float* __restrict__ catL,
                    const float* __restrict__ catR,
                    const float* __restrict__ tin,
                    const float* __restrict__ wgt,
                    const float* __restrict__ bias,
                    const float* __restrict__ bn_g,
                    const float* __restrict__ bn_b,
                    const float* __restrict__ bn_m,
                    const float* __restrict__ bn_v,
                    float* __restrict__ out)
{
    extern __shared__ unsigned char csm[];
    ull*   s_w2 = (ull*)csm;
    float* s_in = (float*)(s_w2 + CONV_W2);
    float* s_sc = s_in + CONV_IN;
    float* s_sh = s_sc + 64;

    const int tid = threadIdx.x;
    const int bz  = blockIdx.z;
    const int oh  = bz & 1;
    const int g   = (bz >> 1) & 3;
    const int b   = (bz >> 3) & 1;
    const int s   = bz >> 4;
    const int sb  = s * B_ + b;
    const int y0  = blockIdx.y * TH;
    const int x0  = blockIdx.x * TW;
    const int gbase = g * 64;
    const int obase = g * 64 + oh * 32;

    const float* cat = s ? catR : catL;

    if (tid < 64) {
        const int ch = gbase + tid;
        const float sc = bn_g[ch] * rsqrtf(bn_v[ch] + 1e-5f);
        s_sc[tid] = sc;
        s_sh[tid] = bn_b[ch] - bn_m[ch] * sc;
    }

    const int og   = tid >> 5;
    const int p    = tid & 31;
    const int rowp = p >> 2;
    const int colp = (p & 3) * 8;

    ull acc2[4][4];
#pragma unroll
    for (int o = 0; o < 4; o++)
#pragma unroll
        for (int q = 0; q < 4; q++) acc2[o][q] = 0ULL;

    const float* inb = (MODE == 1)
        ? cat + (size_t)(b * C4_ + gbase) * HW_
        : tin + (size_t)(sb * C4_ + gbase) * HW_;

    __syncthreads();

    float rin[11];
    float rwv[9];

    auto loadRegs = [&](int icb) {
#pragma unroll
        for (int t = 0; t < 11; t++) {
            const int idx = tid + t * 256;
            float v = 0.f;
            if (idx < IN_ELEMS) {
                const int c   = idx / 340;
                const int rem = idx - c * 340;
                const int r   = rem / 34;
                const int cc  = rem - r * 34;
                const int gy  = y0 - 1 + r;
                const int gx  = x0 - 1 + cc;
                if ((unsigned)gy < (unsigned)H_ && (unsigned)gx < (unsigned)W_) {
                    v = inb[(size_t)(icb + c) * HW_ + gy * W_ + gx];
                    if (MODE == 1)
                        v = v * s_sc[icb + c] + s_sh[icb + c];
                }
            }
            rin[t] = v;
        }
#pragma unroll
        for (int t = 0; t < 9; t++) {
            const int idx = tid + t * 256;
            const int oc  = idx / 72;
            const int r   = idx - oc * 72;
            const int c   = r / 9;
            const int tap = r - c * 9;
            rwv[t] = wgt[(size_t)(obase + oc) * 576 + (icb + c) * 9 + tap];
        }
    };

    auto storeRegs = [&]() {
#pragma unroll
        for (int t = 0; t < 11; t++) {
            const int idx = tid + t * 256;
            if (idx < IN_ELEMS) {
                const int c   = idx / 340;
                const int rem = idx - c * 340;
                const int r   = rem / 34;
                const int cc  = rem - r * 34;
                s_in[(c * 10 + r) * INPITCH + cc] = rin[t];
            }
        }
#pragma unroll
        for (int t = 0; t < 9; t++)
            s_w2[tid + t * 256] = pk2(rwv[t], rwv[t]);
    };

    loadRegs(0);

#pragma unroll 1
    for (int step = 0; step < 8; step++) {
        if (step) __syncthreads();
        storeRegs();
        __syncthreads();
        if (step < 7) loadRegs((step + 1) * ICB);

#pragma unroll 2
        for (int c = 0; c < ICB; c++) {
            float xv[3][10];
#pragma unroll
            for (int kh = 0; kh < 3; kh++) {
                const float* rp = &s_in[(c * 10 + rowp + kh) * INPITCH + colp];
#pragma unroll
                for (int t5 = 0; t5 < 5; t5++) {
                    const float2 v = ((const float2*)rp)[t5];
                    xv[kh][2 * t5]     = v.x;
                    xv[kh][2 * t5 + 1] = v.y;
                }
            }
            const ull* wbase = &s_w2[(og * 4) * 72 + c * 9];
#pragma unroll
            for (int kh = 0; kh < 3; kh++) {
#pragma unroll
                for (int t = 0; t < 3; t++) {
                    const int tap = kh * 3 + t;
                    const ull xp0 = pk2(xv[kh][t],     xv[kh][t + 1]);
                    const ull xp1 = pk2(xv[kh][t + 2], xv[kh][t + 3]);
                    const ull xp2 = pk2(xv[kh][t + 4], xv[kh][t + 5]);
                    const ull xp3 = pk2(xv[kh][t + 6], xv[kh][t + 7]);
#pragma unroll
                    for (int o = 0; o < 4; o++) {
                        const ull w = wbase[o * 72 + tap];
                        fma2(acc2[o][0], w, xp0);
                        fma2(acc2[o][1], w, xp1);
                        fma2(acc2[o][2], w, xp2);
                        fma2(acc2[o][3], w, xp3);
                    }
                }
            }
        }
    }

    const float* catb = cat + (size_t)(b * C4_ + obase) * HW_;
    float*       outb = out + (size_t)(sb * C4_ + obase) * HW_;
    const int y = y0 + rowp;
#pragma unroll
    for (int o = 0; o < 4; o++) {
        const int oc  = og * 4 + o;
        const int cig = oh * 32 + oc;
        const float bv = bias[obase + oc];
#pragma unroll
        for (int pq = 0; pq < 4; pq++) {
            float v0, v1;
            unpk2(acc2[o][pq], v0, v1);
#pragma unroll
            for (int half = 0; half < 2; half++) {
                const int x = x0 + colp + 2 * pq + half;
                float v = (half ? v1 : v0) + bv;
                if (MODE == 1) {
                    v = (v > 0.f) ? v : 0.1f * v;
                } else {
                    const float cv = catb[(size_t)oc * HW_ + y * W_ + x];
                    v += cv * s_sc[cig] + s_sh[cig];
                }
                outb[(size_t)oc * HW_ + y * W_ + x] = v;
            }
        }
    }
}

// ---------------------------------------------------------------------------
// Grouped 1x1 conv -> QUAD-INTERLEAVED output [b][ch/4][h][w][4].
// ---------------------------------------------------------------------------
__global__ __launch_bounds__(256)
void conv1x1_kernel(const float* __restrict__ in,    // t2 [sb][256][HW]
                    const float* __restrict__ bqw, const float* __restrict__ bqb,
                    const float* __restrict__ bsw, const float* __restrict__ bsb,
                    float* __restrict__ Q4, float* __restrict__ K4)
{
    __shared__ ulonglong2 s_wt2[64 * 8];   // [ic][ocpair], 8KB

    const int tid = threadIdx.x;
    const int bz  = blockIdx.z;
    const int s   = bz >> 3;
    const int b   = (bz >> 2) & 1;
    const int g   = bz & 3;

    const float* wsel = s ? bsw : bqw;
    const float* bsel = s ? bsb : bqb;

    for (int idx = tid; idx < 512; idx += 256) {
        const int ic = idx >> 3;
        const int op = idx & 7;
        const float wa = wsel[(g * 16 + 2 * op)     * 64 + ic];
        const float wb = wsel[(g * 16 + 2 * op + 1) * 64 + ic];
        s_wt2[idx] = make_ulonglong2(pk2(wa, wa), pk2(wb, wb));
    }
    __syncthreads();

    const int px0 = blockIdx.x * 1024 + tid * 4;
    const float* ip = in + (size_t)((s * B_ + b) * C4_ + g * 64) * HW_ + px0;

    ull acc[16][2];
#pragma unroll
    for (int o = 0; o < 16; o++) {
        const float bv = bsel[g * 16 + o];
        acc[o][0] = pk2(bv, bv);
        acc[o][1] = pk2(bv, bv);
    }

    for (int ic = 0; ic < 64; ic++) {
        const float4 v = *(const float4*)&ip[(size_t)ic * HW_];
        const ull v01 = pk2(v.x, v.y);
        const ull v23 = pk2(v.z, v.w);
        const ulonglong2* wp = &s_wt2[ic * 8];
#pragma unroll
        for (int op = 0; op < 8; op++) {
            const ulonglong2 w = wp[op];
            fma2(acc[2 * op][0],     w.x, v01);
            fma2(acc[2 * op][1],     w.x, v23);
            fma2(acc[2 * op + 1][0], w.y, v01);
            fma2(acc[2 * op + 1][1], w.y, v23);
        }
    }

    float val[16][4];
#pragma unroll
    for (int o = 0; o < 16; o++) {
        unpk2(acc[o][0], val[o][0], val[o][1]);
        unpk2(acc[o][1], val[o][2], val[o][3]);
    }

    float* dst = s ? K4 : Q4;
#pragma unroll
    for (int q = 0; q < 4; q++) {
        float4* qp = (float4*)(dst + (size_t)((b * 16 + g * 4 + q) * HW_ + px0) * 4);
#pragma unroll
        for (int px = 0; px < 4; px++)
            qp[px] = make_float4(val[4 * q][px], val[4 * q + 1][px],
                                 val[4 * q + 2][px], val[4 * q + 3][px]);
    }
}

// ---------------------------------------------------------------------------
// Attention kernel v4: 8 chunks of 8 channels (2 quads), quad-interleaved
// sources (one LDG.128 per staged float4), register-resident logit accs,
// smem ~59KB -> 3 blocks/SM. Grid (H, B, dir).
// ---------------------------------------------------------------------------
constexpr int ROWP4  = 105;
constexpr int CSTR4  = 8 * ROWP4 + 5;   // 845
constexpr int NQUAD  = 2;               // quads per chunk (8 channels)
constexpr int WIN_F4 = NQUAD * CSTR4;   // 1690 float4 = 27040 B
constexpr int CEN_F4 = NQUAD * 96;      // 192 float4 = 3072 B
constexpr int MPITCH = 66;
constexpr int M_F    = 96 * MPITCH;     // 25344 B
constexpr int OUT_F  = 8 * 96;          // 3072 B
constexpr int ATT_SMEM = WIN_F4 * 16 + CEN_F4 * 16 + M_F * 4 + OUT_F * 4 + 5 * 96 * 4;

__global__ __launch_bounds__(256, 3)
void attention_kernel(const float* __restrict__ Q4, const float* __restrict__ K4,
                      const float* __restrict__ X4,
                      const float* __restrict__ xL, const float* __restrict__ xR,
                      const int* __restrict__ dL, const int* __restrict__ dR,
                      float* __restrict__ outL, float* __restrict__ outR)
{
    extern __shared__ float smem[];
    float4* s_win4 = (float4*)smem;                 // WIN_F4
    float4* s_cen4 = s_win4 + WIN_F4;               // CEN_F4
    float*  s_M    = (float*)(s_cen4 + CEN_F4);     // M_F
    float*  s_out  = s_M + M_F;                     // OUT_F
    int*    s_cc   = (int*)(s_out + OUT_F);         // 96
    int*    s_cv   = s_cc + 96;                     // 96
    int*    s_sval = s_cv + 96;                     // 96
    int*    s_vval = s_sval + 96;                   // 96
    float*  s_mask = (float*)(s_vval + 96);         // 96

    const int i   = blockIdx.x;
    const int b   = blockIdx.y;
    const int z   = blockIdx.z;                     // 0=r2l, 1=l2r
    const int tid = threadIdx.x;

    if (tid < 96) {
        const int j  = tid;
        const int dl = dL[(b * H_ + i) * W_ + j];
        const int dr = dR[(b * H_ + i) * W_ + j];
        const int cr = max(j - dl, 0);
        const int cl = min(j + dr, W_ - 1);
        const int rowok = (i + 4) < H_;
        const int vR = (rowok && cr < W_ - 4) ? 1 : 0;
        const int vL = (rowok && cl < W_ - 4) ? 1 : 0;
        s_cc[j]   = z ? cl : cr;
        s_cv[j]   = cr;                             // value coords always r2l
        s_sval[j] = z ? vL : vR;
        s_vval[j] = vR;
        s_mask[j] = z ? ((j + dr <= W_ - 1) ? 1.f : 0.f)
                      : ((j - dl >= 0)      ? 1.f : 0.f);
    }
    const float4 zero4 = make_float4(0.f, 0.f, 0.f, 0.f);
    for (int idx = tid; idx < WIN_F4; idx += 256) s_win4[idx] = zero4;
    __syncthreads();

    const float4* win4src = (const float4*)(z ? Q4 : K4);
    const float4* cen4src = (const float4*)(z ? K4 : Q4);
    const int kbit  = tid & 1;
    const int koff  = kbit * 32;
    const int aoff4 = kbit * 4 * ROWP4;
    const int jlog  = tid >> 1;
    const int cc    = (tid < 192) ? s_cc[jlog] : 0;

    // ---- logits: 8 chunks of 2 quads; acc stays in registers ----
    float acc[32];
#pragma unroll
    for (int kk = 0; kk < 32; kk++) acc[kk] = 0.f;

    for (int cb = 0; cb < 8; cb++) {
        for (int idx = tid; idx < NQUAD * 768; idx += 256) {
            const int q   = idx / 768;
            const int rem = idx - q * 768;           // a*96 + col
            const int a   = rem / 96;
            const int col = rem - a * 96;
            const int gy  = i - 4 + a;
            float4 v = zero4;
            if ((unsigned)gy < (unsigned)H_)
                v = win4src[(size_t)(b * 16 + cb * 2 + q) * HW_ + gy * W_ + col];
            s_win4[q * CSTR4 + a * ROWP4 + 4 + col] = v;
        }
        if (tid < NQUAD * 96) {
            const int q = tid / 96, j = tid - q * 96;
            s_cen4[tid] = cen4src[(size_t)(b * 16 + cb * 2 + q) * HW_ + i * W_ + j];
        }
        __syncthreads();

        if (tid < 192) {
#pragma unroll
            for (int q = 0; q < NQUAD; q++) {
                const float4 cen = s_cen4[q * 96 + jlog];
                const float4* wb = s_win4 + q * CSTR4 + cc + aoff4;
#pragma unroll
                for (int kk = 0; kk < 32; kk++) {
                    const float4 w = wb[(kk >> 3) * ROWP4 + (kk & 7)];
                    acc[kk] = fmaf(cen.x, w.x,
                              fmaf(cen.y, w.y,
                              fmaf(cen.z, w.z,
                              fmaf(cen.w, w.w, acc[kk]))));
                }
            }
        }
        __syncthreads();
    }

    if (tid < 192) {
        float* Mrow = s_M + jlog * MPITCH + koff;
#pragma unroll
        for (int kk = 0; kk < 32; kk++) Mrow[kk] = acc[kk];
    }
    __syncthreads();

    // ---- softmax ----
    if (tid < 96) {
        float* row = s_M + tid * MPITCH;
        if (!s_sval[tid]) {
#pragma unroll
            for (int k = 0; k < 64; k++) row[k] = 1.f / 64.f;
        } else {
            float mx = row[0];
#pragma unroll
            for (int k = 1; k < 64; k++) mx = fmaxf(mx, row[k]);
            float ssum = 0.f;
#pragma unroll
            for (int k = 0; k < 64; k++) {
                const float e = __expf(row[k] - mx);
                row[k] = e; ssum += e;
            }
            const float inv = 1.f / ssum;
#pragma unroll
            for (int k = 0; k < 64; k++) row[k] *= inv;
        }
    }
    __syncthreads();

    // ---- value pass: 8 chunks of 2 quads ----
    // value source: dir 0 uses xR (side 1), dir 1 uses xL (side 0)
    const float4* val4src = (const float4*)X4 + (size_t)(z ? 0 : 1) * B_ * 16 * HW_;
    const float*  basesrc = z ? xR : xL;
    float*        outdst  = z ? outR : outL;
    const int quad = tid & 1;
    const int jg   = tid >> 1;           // 0..127, active < 96

    for (int cb = 0; cb < 8; cb++) {
        for (int idx = tid; idx < NQUAD * 768; idx += 256) {
            const int q   = idx / 768;
            const int rem = idx - q * 768;
            const int a   = rem / 96;
            const int col = rem - a * 96;
            const int gy  = i - 4 + a;
            float4 v = zero4;
            if ((unsigned)gy < (unsigned)H_)
                v = val4src[(size_t)(b * 16 + cb * 2 + q) * HW_ + gy * W_ + col];
            s_win4[q * CSTR4 + a * ROWP4 + 4 + col] = v;
        }
        __syncthreads();

        if (jg < 96) {
            const int j = jg;
            float a0 = 0.f, a1 = 0.f, a2 = 0.f, a3 = 0.f;
            if (s_vval[j]) {
                const float4* wb   = s_win4 + quad * CSTR4 + s_cv[j];
                const float*  Mrow = s_M + j * MPITCH;
#pragma unroll
                for (int kp = 0; kp < 32; kp++) {
                    const float2 mv = *(const float2*)(Mrow + 2 * kp);
                    const int k0 = 2 * kp, k1 = 2 * kp + 1;
                    const float4 w0 = wb[(k0 >> 3) * ROWP4 + (k0 & 7)];
                    const float4 w1 = wb[(k1 >> 3) * ROWP4 + (k1 & 7)];
                    a0 = fmaf(mv.x, w0.x, fmaf(mv.y, w1.x, a0));
                    a1 = fmaf(mv.x, w0.y, fmaf(mv.y, w1.y, a1));
                    a2 = fmaf(mv.x, w0.z, fmaf(mv.y, w1.z, a2));
                    a3 = fmaf(mv.x, w0.w, fmaf(mv.y, w1.w, a3));
                }
            }
            const float mk = s_mask[j];
            s_out[(4 * quad + 0) * 96 + j] = a0 * mk;
            s_out[(4 * quad + 1) * 96 + j] = a1 * mk;
            s_out[(4 * quad + 2) * 96 + j] = a2 * mk;
            s_out[(4 * quad + 3) * 96 + j] = a3 * mk;
        }
        __syncthreads();

        for (int t = 0; t < 3; t++) {
            const int idx = tid + t * 256;
            const int c = idx / 96, j = idx - c * 96;
            const size_t gidx = ((size_t)(b * C_ + cb * 8 + c) * H_ + i) * W_ + j;
            outdst[gidx] = basesrc[gidx] + s_out[idx];
        }
        __syncthreads();
    }
}

// ---------------------------------------------------------------------------
// Host launcher
// ---------------------------------------------------------------------------
extern "C" void kernel_launch(void* const* d_in, const int* in_sizes, int n_in,
                              void* d_out, int out_size)
{
    const float *xL, *xR, *catL, *catR;
    const float *bng, *bnb, *bnm, *bnv, *w1, *b1, *w2, *b2, *bqw, *bqb, *bsw, *bsb;
    const int *dL, *dR;

    const bool dict_order = (n_in >= 18) && (in_sizes[4] == B_ * H_ * W_);
    if (dict_order) {
        xL   = (const float*)d_in[0];  xR   = (const float*)d_in[1];
        catL = (const float*)d_in[2];  catR = (const float*)d_in[3];
        dL   = (const int*)  d_in[4];  dR   = (const int*)  d_in[5];
        bng  = (const float*)d_in[6];  bnb  = (const float*)d_in[7];
        bnm  = (const float*)d_in[8];  bnv  = (const float*)d_in[9];
        w1   = (const float*)d_in[10]; b1   = (const float*)d_in[11];
        w2   = (const float*)d_in[12]; b2   = (const float*)d_in[13];
        bqw  = (const float*)d_in[14]; bqb  = (const float*)d_in[15];
        bsw  = (const float*)d_in[16]; bsb  = (const float*)d_in[17];
    } else {
        xL   = (const float*)d_in[0];  xR   = (const float*)d_in[1];
        catL = (const float*)d_in[2];  catR = (const float*)d_in[3];
        bng  = (const float*)d_in[4];  bnb  = (const float*)d_in[5];
        bnm  = (const float*)d_in[6];  bnv  = (const float*)d_in[7];
        w1   = (const float*)d_in[8];  b1   = (const float*)d_in[9];
        w2   = (const float*)d_in[10]; b2   = (const float*)d_in[11];
        bqw  = (const float*)d_in[12]; bqb  = (const float*)d_in[13];
        bsw  = (const float*)d_in[14]; bsb  = (const float*)d_in[15];
        dL   = (const int*)  d_in[16]; dR   = (const int*)  d_in[17];
    }

    float *t1, *t2, *Q4p, *K4p, *X4p;
    cudaGetSymbolAddress((void**)&t1, g_t1);
    cudaGetSymbolAddress((void**)&t2, g_t2);
    cudaGetSymbolAddress((void**)&Q4p, g_Q4);
    cudaGetSymbolAddress((void**)&K4p, g_K4);
    cudaGetSymbolAddress((void**)&X4p, g_X4);

    cudaFuncSetAttribute(conv3x3_kernel<1>,
                         cudaFuncAttributeMaxDynamicSharedMemorySize, CONV_SMEM);
    cudaFuncSetAttribute(conv3x3_kernel<2>,
                         cudaFuncAttributeMaxDynamicSharedMemorySize, CONV_SMEM);
    cudaFuncSetAttribute(attention_kernel,
                         cudaFuncAttributeMaxDynamicSharedMemorySize, ATT_SMEM);

    const dim3 cgrid(W_ / TW, H_ / TH, NSB * 8);   // 768 blocks

    // repack x first (independent of conv chain; overlaps on stream order)
    repack_kernel<<<(2 * B_ * 16 * HW_ + 255) / 256, 256>>>(xL, xR, X4p);

    conv3x3_kernel<1><<<cgrid, 256, CONV_SMEM>>>(catL, catR, nullptr, w1, b1,
                                                 bng, bnb, bnm, bnv, t1);
    conv3x3_kernel<2><<<cgrid, 256, CONV_SMEM>>>(catL, catR, t1, w2, b2,
                                                 bng, bnb, bnm, bnv, t2);
    conv1x1_kernel<<<dim3(6, 1, 16), 256>>>(t2, bqw, bqb, bsw, bsb, Q4p, K4p);

    float* outL = (float*)d_out;
    float* outR = outL + (size_t)B_ * C_ * HW_;
    attention_kernel<<<dim3(H_, B_, 2), 256, ATT_SMEM>>>(Q4p, K4p, X4p,
                                                         xL, xR, dL, dR,
                                                         outL, outR);
}